// round 2
// baseline (speedup 1.0000x reference)
#include <cuda_runtime.h>
#include <math.h>

#define D_MODEL 2048
#define D_STATE 16
#define D_CONV  4
#define B_SZ    2
#define T_LEN   2048
#define M_TOK   (B_SZ * T_LEN)          /* 4096 tokens */
#define N_XZ    (2 * D_MODEL)           /* 4096 */
#define N_PROJ  (D_MODEL + 2 * D_STATE) /* 2080 */

// ---------------- scratch (static device arrays; no runtime allocation) ----
// g_xn doubles as y-buffer: xn is dead after GEMM1, y is born at the scan.
__device__ float g_xn  [(size_t)M_TOK * D_MODEL];  // rmsnorm out, later gated y
__device__ float g_xz  [(size_t)M_TOK * N_XZ];     // in_proj out (x_branch | z)
__device__ float g_xssm[(size_t)M_TOK * D_MODEL];  // conv+silu out
__device__ float g_proj[(size_t)M_TOK * N_PROJ];   // x_proj out (delta | B | C)

// ---------------------------------------------------------------- rmsnorm --
__global__ __launch_bounds__(256)
void rmsnorm_kernel(const float* __restrict__ x, const float* __restrict__ w)
{
    const int row = blockIdx.x;
    const int tid = threadIdx.x;
    const float4* xr = (const float4*)(x + (size_t)row * D_MODEL);

    float4 v0 = xr[tid];
    float4 v1 = xr[tid + 256];
    float ss = v0.x*v0.x + v0.y*v0.y + v0.z*v0.z + v0.w*v0.w
             + v1.x*v1.x + v1.y*v1.y + v1.z*v1.z + v1.w*v1.w;

    #pragma unroll
    for (int o = 16; o > 0; o >>= 1) ss += __shfl_xor_sync(0xffffffffu, ss, o);

    __shared__ float red[8];
    __shared__ float s_scale;
    if ((tid & 31) == 0) red[tid >> 5] = ss;
    __syncthreads();
    if (tid == 0) {
        float t = 0.f;
        #pragma unroll
        for (int i = 0; i < 8; ++i) t += red[i];
        s_scale = rsqrtf(t * (1.0f / D_MODEL) + 1e-6f);
    }
    __syncthreads();
    const float sc = s_scale;

    const float4* w4 = (const float4*)w;
    float4 wv0 = w4[tid], wv1 = w4[tid + 256];
    float4 o0, o1;
    o0.x = v0.x*sc*wv0.x; o0.y = v0.y*sc*wv0.y; o0.z = v0.z*sc*wv0.z; o0.w = v0.w*sc*wv0.w;
    o1.x = v1.x*sc*wv1.x; o1.y = v1.y*sc*wv1.y; o1.z = v1.z*sc*wv1.z; o1.w = v1.w*sc*wv1.w;
    float4* outr = (float4*)(g_xn + (size_t)row * D_MODEL);
    outr[tid]       = o0;
    outr[tid + 256] = o1;
}

// ------------------------------------------------------------------- sgemm --
// C[M,N] = A[M,K] @ B[N,K]^T   (both row-major; "NT" gemm)
// BM=BN=128, BK=16, 256 threads, 8x8 per thread in split-fragment layout
// (rows ty*4 & 64+ty*4, cols tx*4 & 64+tx*4) for conflict-free LDS.128.
// EPI=1 adds residual (same [M,N] layout as C).
template<int EPI>
__global__ __launch_bounds__(256)
void sgemm_nt(const float* __restrict__ A, const float* __restrict__ Bw,
              float* __restrict__ C, const float* __restrict__ resid,
              int N, int K)
{
    constexpr int BM = 128, BN = 128, BK = 16;
    __shared__ float As[BK][BM + 4];
    __shared__ float Bs[BK][BN + 4];

    const int tid = threadIdx.x;
    const int m0 = blockIdx.y * BM;
    const int n0 = blockIdx.x * BN;
    const int tx = tid & 15;
    const int ty = tid >> 4;

    const int lin0 = tid, lin1 = tid + 256;
    const int ar0 = lin0 >> 2, aq0 = (lin0 & 3) * 4;
    const int ar1 = lin1 >> 2, aq1 = (lin1 & 3) * 4;

    const float* Ap0 = A + (size_t)(m0 + ar0) * K + aq0;
    const float* Ap1 = A + (size_t)(m0 + ar1) * K + aq1;
    const bool bv0 = (n0 + ar0) < N;
    const bool bv1 = (n0 + ar1) < N;
    const float* Bp0 = Bw + (size_t)(bv0 ? (n0 + ar0) : 0) * K + aq0;
    const float* Bp1 = Bw + (size_t)(bv1 ? (n0 + ar1) : 0) * K + aq1;

    float acc[8][8];
    #pragma unroll
    for (int i = 0; i < 8; ++i)
        #pragma unroll
        for (int j = 0; j < 8; ++j) acc[i][j] = 0.f;

    const float4 z4 = make_float4(0.f, 0.f, 0.f, 0.f);

    float4 a0 = *(const float4*)(Ap0);
    float4 a1 = *(const float4*)(Ap1);
    float4 b0 = bv0 ? *(const float4*)(Bp0) : z4;
    float4 b1 = bv1 ? *(const float4*)(Bp1) : z4;

    auto store_smem = [&](float4 ta0, float4 ta1, float4 tb0, float4 tb1) {
        As[aq0+0][ar0] = ta0.x; As[aq0+1][ar0] = ta0.y; As[aq0+2][ar0] = ta0.z; As[aq0+3][ar0] = ta0.w;
        As[aq1+0][ar1] = ta1.x; As[aq1+1][ar1] = ta1.y; As[aq1+2][ar1] = ta1.z; As[aq1+3][ar1] = ta1.w;
        Bs[aq0+0][ar0] = tb0.x; Bs[aq0+1][ar0] = tb0.y; Bs[aq0+2][ar0] = tb0.z; Bs[aq0+3][ar0] = tb0.w;
        Bs[aq1+0][ar1] = tb1.x; Bs[aq1+1][ar1] = tb1.y; Bs[aq1+2][ar1] = tb1.z; Bs[aq1+3][ar1] = tb1.w;
    };
    auto compute = [&]() {
        #pragma unroll
        for (int kk = 0; kk < BK; ++kk) {
            float af[8], bf[8];
            *(float4*)(af)     = *(const float4*)(&As[kk][ty * 4]);
            *(float4*)(af + 4) = *(const float4*)(&As[kk][64 + ty * 4]);
            *(float4*)(bf)     = *(const float4*)(&Bs[kk][tx * 4]);
            *(float4*)(bf + 4) = *(const float4*)(&Bs[kk][64 + tx * 4]);
            #pragma unroll
            for (int i = 0; i < 8; ++i)
                #pragma unroll
                for (int j = 0; j < 8; ++j)
                    acc[i][j] = fmaf(af[i], bf[j], acc[i][j]);
        }
    };

    store_smem(a0, a1, b0, b1);
    __syncthreads();

    const int nt = K / BK;
    for (int t = 1; t < nt; ++t) {
        const int kt = t * BK;
        float4 na0 = *(const float4*)(Ap0 + kt);
        float4 na1 = *(const float4*)(Ap1 + kt);
        float4 nb0 = bv0 ? *(const float4*)(Bp0 + kt) : z4;
        float4 nb1 = bv1 ? *(const float4*)(Bp1 + kt) : z4;
        compute();
        __syncthreads();
        store_smem(na0, na1, nb0, nb1);
        __syncthreads();
    }
    compute();

    #pragma unroll
    for (int ih = 0; ih < 2; ++ih) {
        #pragma unroll
        for (int i = 0; i < 4; ++i) {
            const int gm = m0 + ih * 64 + ty * 4 + i;
            #pragma unroll
            for (int iw = 0; iw < 2; ++iw) {
                #pragma unroll
                for (int j = 0; j < 4; ++j) {
                    const int gn = n0 + iw * 64 + tx * 4 + j;
                    if (gn < N) {
                        float v = acc[ih * 4 + i][iw * 4 + j];
                        if (EPI) v += resid[(size_t)gm * N + gn];
                        C[(size_t)gm * N + gn] = v;
                    }
                }
            }
        }
    }
}

// ------------------------------------------------------ depthwise conv+silu -
__global__ __launch_bounds__(256)
void conv_silu_kernel(const float* __restrict__ cw, const float* __restrict__ cb)
{
    const int idx = blockIdx.x * 256 + threadIdx.x;   // < M_TOK*D_MODEL
    const int d   = idx & (D_MODEL - 1);
    const int row = idx >> 11;                        // b*T + t
    const int t   = row & (T_LEN - 1);

    const float w0 = cw[d * 4 + 0], w1 = cw[d * 4 + 1];
    const float w2 = cw[d * 4 + 2], w3 = cw[d * 4 + 3];

    float acc = cb[d] + w3 * g_xz[(size_t)row * N_XZ + d];
    if (t >= 1) acc = fmaf(w2, g_xz[(size_t)(row - 1) * N_XZ + d], acc);
    if (t >= 2) acc = fmaf(w1, g_xz[(size_t)(row - 2) * N_XZ + d], acc);
    if (t >= 3) acc = fmaf(w0, g_xz[(size_t)(row - 3) * N_XZ + d], acc);

    const float s = acc / (1.0f + __expf(-acc));      // silu
    g_xssm[(size_t)row * D_MODEL + d] = s;
}

// ------------------------------------------------------------ selective scan -
// One half-warp (16 lanes = 16 states) per (b, d) channel. 256 threads/block
// -> 16 channels/block; grid = B * (D_MODEL/16) = 256 blocks.
// Writes gated y into g_xn (xn is dead by now).
__global__ __launch_bounds__(256)
void scan_kernel(const float* __restrict__ h0, const float* __restrict__ A_log,
                 const float* __restrict__ Dvec, float* __restrict__ h_out)
{
    constexpr int TC = 32;
    const int blk  = blockIdx.x;
    const int b    = blk >> 7;          // / 128
    const int d0   = (blk & 127) * 16;
    const int tid  = threadIdx.x;
    const int warp = tid >> 5;
    const int lane = tid & 31;
    const int half = lane >> 4;
    const int n    = lane & 15;
    const int lc   = warp * 2 + half;   // local channel 0..15
    const int dch  = d0 + lc;

    const float A_n  = -__expf(A_log[dch * D_STATE + n]);
    const float Dd   = Dvec[dch];
    float h = h0[((size_t)b * D_MODEL + dch) * D_STATE + n];

    __shared__ float sD[TC][16];
    __shared__ float sX[TC][16];
    __shared__ float sB[TC][16];
    __shared__ float sC[TC][16];
    __shared__ float sY[TC][16];

    for (int c = 0; c < T_LEN / TC; ++c) {
        const int t0 = c * TC;
        #pragma unroll
        for (int i = tid; i < TC * 16; i += 256) {
            const int tt = i >> 4, dd = i & 15;
            const size_t row = (size_t)(b * T_LEN + t0 + tt);
            const float dr = g_proj[row * N_PROJ + d0 + dd];
            sD[tt][dd] = (dr > 20.f) ? dr : log1pf(__expf(dr));   // softplus
            sX[tt][dd] = g_xssm[row * D_MODEL + d0 + dd];
            sB[tt][dd] = g_proj[row * N_PROJ + D_MODEL + dd];
            sC[tt][dd] = g_proj[row * N_PROJ + D_MODEL + D_STATE + dd];
        }
        __syncthreads();

        #pragma unroll 4
        for (int tt = 0; tt < TC; ++tt) {
            const float dt = sD[tt][lc];
            const float xv = sX[tt][lc];
            const float bv = sB[tt][n];
            const float cv = sC[tt][n];
            h = fmaf(__expf(dt * A_n), h, (dt * xv) * bv);
            float p = h * cv;
            p += __shfl_xor_sync(0xffffffffu, p, 8);
            p += __shfl_xor_sync(0xffffffffu, p, 4);
            p += __shfl_xor_sync(0xffffffffu, p, 2);
            p += __shfl_xor_sync(0xffffffffu, p, 1);
            if (n == 0) sY[tt][lc] = fmaf(Dd, xv, p);
        }
        __syncthreads();

        // gated coalesced store: y = y_scan * silu(z)  -> g_xn (reused)
        #pragma unroll
        for (int i = tid; i < TC * 16; i += 256) {
            const int tt = i >> 4, dd = i & 15;
            const size_t row = (size_t)(b * T_LEN + t0 + tt);
            const float z = g_xz[row * N_XZ + D_MODEL + d0 + dd];
            g_xn[row * D_MODEL + d0 + dd] = sY[tt][dd] * (z / (1.0f + __expf(-z)));
        }
        __syncthreads();
    }

    if (h_out)
        h_out[((size_t)b * D_MODEL + dch) * D_STATE + n] = h;
}

// ------------------------------------- pointer-fetch helpers (device side) --
// Kernels that need the scratch buffers as GEMM operands get them via these
// tiny launches? No — simpler: wrapper kernels below take no scratch pointers;
// for sgemm we need raw pointers. Fetch them with a 1-thread kernel into a
// __device__ pointer table read back? Not graph-legal. Instead: the GEMM
// wrappers below are thin __global__ shims that call into sgemm logic with
// global-array addresses taken in device code. To avoid duplicating the GEMM,
// we instead launch sgemm_nt with addresses obtained at *host* side via
// cudaGetSymbolAddress — removed due to suspected capture issue. Solution:
// device-side address-of on __device__ arrays is constant; expose via
// constexpr-like shim kernels:
__global__ void gemm1_shim();  // fwd decl not needed; we use templated approach

// Simpler and robust: wrapper kernels that compute the pointers in device code
// and delegate by inlining. We re-instantiate sgemm_nt via a device function.
// (The templated sgemm_nt above is already a __global__; we create thin
// variants bound to the scratch arrays.)

template<int EPI>
__device__ __forceinline__
void sgemm_body(const float* A, const float* Bw, float* C,
                const float* resid, int N, int K);

// To keep one GEMM implementation, redefine sgemm_nt to call sgemm_body.
// (sgemm_nt above already contains the body; the wrappers below simply pass
// device-linkage addresses of the globals, which is legal in __global__
// argument expressions at launch time ONLY from device code. From host code
// we cannot take &g_xn. So: use launch-parameter-free wrapper kernels.)

__global__ __launch_bounds__(256) void gemm_xz_kernel(const float* __restrict__ W)
{
    // thin trampoline not feasible without code dup; instead this kernel is
    // never launched. Host uses legacy symbol binding below.
}

// --------------------------------------------------------------------- host -
// NOTE on symbol addresses: we avoid cudaGetSymbolAddress inside
// kernel_launch (suspected container/capture issue) by resolving the five
// scratch symbols ONCE via static initialization of host-side pointers using
// cudaGetSymbolAddress at first call, guarded to happen before any capture
// (the harness calls kernel_launch for correctness before capturing; the
// resolved addresses are pure data thereafter and identical every call,
// keeping kernel_launch deterministic).
static float* s_xn   = nullptr;
static float* s_xz   = nullptr;
static float* s_xssm = nullptr;
static float* s_proj = nullptr;
static bool   s_init = false;

extern "C" void kernel_launch(void* const* d_in, const int* in_sizes, int n_in,
                              void* d_out, int out_size)
{
    const float* x          = (const float*)d_in[0];
    const float* h0         = (const float*)d_in[1];
    const float* norm_w     = (const float*)d_in[2];
    const float* in_proj_w  = (const float*)d_in[3];
    const float* conv_w     = (const float*)d_in[4];
    const float* conv_b     = (const float*)d_in[5];
    const float* x_proj_w   = (const float*)d_in[6];
    const float* A_log      = (const float*)d_in[7];
    const float* Dvec       = (const float*)d_in[8];
    const float* out_proj_w = (const float*)d_in[9];

    if (!s_init) {
        cudaGetSymbolAddress((void**)&s_xn,   g_xn);
        cudaGetSymbolAddress((void**)&s_xz,   g_xz);
        cudaGetSymbolAddress((void**)&s_xssm, g_xssm);
        cudaGetSymbolAddress((void**)&s_proj, g_proj);
        s_init = true;
    }

    float* out = (float*)d_out;
    const size_t out_elems = (size_t)M_TOK * D_MODEL;
    float* h_out = ((size_t)out_size >= out_elems + (size_t)B_SZ * D_MODEL * D_STATE)
                       ? out + out_elems : nullptr;

    // 1. rmsnorm -> g_xn
    rmsnorm_kernel<<<M_TOK, 256>>>(x, norm_w);

    // 2. xz = xn @ in_proj_w^T   (M=4096, N=4096, K=2048)
    sgemm_nt<0><<<dim3(N_XZ / 128, M_TOK / 128), 256>>>(
        s_xn, in_proj_w, s_xz, nullptr, N_XZ, D_MODEL);

    // 3. depthwise causal conv + silu -> g_xssm
    conv_silu_kernel<<<(M_TOK * D_MODEL) / 256, 256>>>(conv_w, conv_b);

    // 4. proj = xssm @ x_proj_w^T   (N=2080, N-guarded)
    sgemm_nt<0><<<dim3((N_PROJ + 127) / 128, M_TOK / 128), 256>>>(
        s_xssm, x_proj_w, s_proj, nullptr, N_PROJ, D_MODEL);

    // 5. selective scan (+softplus, +silu(z) gating) -> y in g_xn; h_new tail
    scan_kernel<<<B_SZ * (D_MODEL / 16), 256>>>(h0, A_log, Dvec, h_out);

    // 6. out = x + y @ out_proj_w^T
    sgemm_nt<1><<<dim3(D_MODEL / 128, M_TOK / 128), 256>>>(
        s_xn, out_proj_w, out, x, D_MODEL, D_MODEL);
}

// round 5
// speedup vs baseline: 1.8004x; 1.8004x over previous
#include <cuda_runtime.h>
#include <cuda_bf16.h>
#include <math.h>
#include <stdint.h>

#define D_MODEL 2048
#define D_STATE 16
#define B_SZ    2
#define T_LEN   2048
#define M_TOK   (B_SZ * T_LEN)          /* 4096 */
#define N_XZ    (2 * D_MODEL)           /* 4096 */
#define N_PROJ  (D_MODEL + 2 * D_STATE) /* 2080 */

// ---------------- scratch (static device arrays) ---------------------------
__device__ __nv_bfloat16 g_a_hi[(size_t)M_TOK * D_MODEL];
__device__ __nv_bfloat16 g_a_lo[(size_t)M_TOK * D_MODEL];
__device__ __nv_bfloat16 g_b_hi[(size_t)N_XZ  * D_MODEL];
__device__ __nv_bfloat16 g_b_lo[(size_t)N_XZ  * D_MODEL];
__device__ float g_xz  [(size_t)M_TOK * N_XZ];
__device__ float g_proj[(size_t)M_TOK * N_PROJ];

// ---------------------------- asm helpers ----------------------------------
#define CP_ASYNC16(dst, src) \
    asm volatile("cp.async.cg.shared.global [%0], [%1], 16;" :: "r"(dst), "l"(src))
#define CP_COMMIT() asm volatile("cp.async.commit_group;" ::: "memory")
#define CP_WAIT(n)  asm volatile("cp.async.wait_group %0;" :: "n"(n) : "memory")
#define LDSM_X4(r0, r1, r2, r3, addr) \
    asm volatile("ldmatrix.sync.aligned.m8n8.x4.shared.b16 {%0,%1,%2,%3}, [%4];" \
                 : "=r"(r0), "=r"(r1), "=r"(r2), "=r"(r3) : "r"(addr))
#define MMA16816(c, a0, a1, a2, a3, b0, b1) \
    asm volatile("mma.sync.aligned.m16n8k16.row.col.f32.bf16.bf16.f32 " \
                 "{%0,%1,%2,%3}, {%4,%5,%6,%7}, {%8,%9}, {%0,%1,%2,%3};" \
                 : "+f"((c)[0]), "+f"((c)[1]), "+f"((c)[2]), "+f"((c)[3]) \
                 : "r"(a0), "r"(a1), "r"(a2), "r"(a3), "r"(b0), "r"(b1))

// ----------------------------- split helpers -------------------------------
__device__ __forceinline__ void split1(float a, __nv_bfloat16& h, __nv_bfloat16& l) {
    h = __float2bfloat16(a);
    l = __float2bfloat16(a - __bfloat162float(h));
}
__device__ __forceinline__ void split4(float4 v, uint2& H, uint2& L) {
    __nv_bfloat16 h0, h1, h2, h3, l0, l1, l2, l3;
    split1(v.x, h0, l0); split1(v.y, h1, l1); split1(v.z, h2, l2); split1(v.w, h3, l3);
    H.x = (uint32_t)__bfloat16_as_ushort(h0) | ((uint32_t)__bfloat16_as_ushort(h1) << 16);
    H.y = (uint32_t)__bfloat16_as_ushort(h2) | ((uint32_t)__bfloat16_as_ushort(h3) << 16);
    L.x = (uint32_t)__bfloat16_as_ushort(l0) | ((uint32_t)__bfloat16_as_ushort(l1) << 16);
    L.y = (uint32_t)__bfloat16_as_ushort(l2) | ((uint32_t)__bfloat16_as_ushort(l3) << 16);
}

// --------------------------------- rmsnorm ---------------------------------
__global__ __launch_bounds__(256)
void rmsnorm_kernel(const float* __restrict__ x, const float* __restrict__ w)
{
    const int row = blockIdx.x;
    const int tid = threadIdx.x;
    const float4* xr = (const float4*)(x + (size_t)row * D_MODEL);
    float4 v0 = xr[tid], v1 = xr[tid + 256];
    float ss = v0.x*v0.x + v0.y*v0.y + v0.z*v0.z + v0.w*v0.w
             + v1.x*v1.x + v1.y*v1.y + v1.z*v1.z + v1.w*v1.w;
    #pragma unroll
    for (int o = 16; o > 0; o >>= 1) ss += __shfl_xor_sync(0xffffffffu, ss, o);
    __shared__ float red[8]; __shared__ float s_scale;
    if ((tid & 31) == 0) red[tid >> 5] = ss;
    __syncthreads();
    if (tid == 0) {
        float t = 0.f;
        #pragma unroll
        for (int i = 0; i < 8; ++i) t += red[i];
        s_scale = rsqrtf(t * (1.0f / D_MODEL) + 1e-6f);
    }
    __syncthreads();
    const float sc = s_scale;
    const float4* w4 = (const float4*)w;
    float4 wv0 = w4[tid], wv1 = w4[tid + 256];
    float4 o0 = make_float4(v0.x*sc*wv0.x, v0.y*sc*wv0.y, v0.z*sc*wv0.z, v0.w*sc*wv0.w);
    float4 o1 = make_float4(v1.x*sc*wv1.x, v1.y*sc*wv1.y, v1.z*sc*wv1.z, v1.w*sc*wv1.w);
    uint2* oh = (uint2*)(g_a_hi + (size_t)row * D_MODEL);
    uint2* ol = (uint2*)(g_a_lo + (size_t)row * D_MODEL);
    uint2 H, L;
    split4(o0, H, L); oh[tid] = H;       ol[tid] = L;
    split4(o1, H, L); oh[tid + 256] = H; ol[tid + 256] = L;
}

// ------------------------------ weight split -------------------------------
__global__ __launch_bounds__(256)
void split_kernel(const float* __restrict__ src, int n4)
{
    const int i = blockIdx.x * 256 + threadIdx.x;
    if (i < n4) {
        float4 v = ((const float4*)src)[i];
        uint2 H, L; split4(v, H, L);
        ((uint2*)g_b_hi)[i] = H;
        ((uint2*)g_b_lo)[i] = L;
    }
}

// ----------------------------- mma.sync GEMM -------------------------------
// C[M,N] = A[M,K] @ B[N,K]^T via bf16 (hi,lo) 3-product split, fp32 accum.
// BM=BN=128, BK=32 bf16; 8 warps, warp tile 64x32 (4x4 m16n8k16 tiles).
// cp.async double-buffered SMEM, rows padded to 40 bf16 (80 B) for
// conflict-free ldmatrix.
#define BK 32
static constexpr int T_ELEM  = 128 * 40;          // padded elems per tile
static constexpr int STG_E   = 4 * T_ELEM;        // A_hi A_lo B_hi B_lo
static constexpr int SMEM_GEMM = 2 * STG_E * 2;   // bytes = 81920

__global__ __launch_bounds__(256, 1)
void gemm_bf3(const __nv_bfloat16* __restrict__ Ahi, const __nv_bfloat16* __restrict__ Alo,
              const __nv_bfloat16* __restrict__ Bhi, const __nv_bfloat16* __restrict__ Blo,
              float* __restrict__ C, const float* __restrict__ resid, int N, int EPI)
{
    extern __shared__ __nv_bfloat16 smem[];
    const uint32_t sbase = (uint32_t)__cvta_generic_to_shared(smem);
    const int tid  = threadIdx.x;
    const int lane = tid & 31;
    const int wid  = tid >> 5;
    const int wm   = wid >> 2;       // 0..1
    const int wn   = wid & 3;        // 0..3
    const int m0   = blockIdx.y * 128;
    const int n0   = blockIdx.x * 128;

    // per-thread cp.async coords (2 x 16B chunks per tile)
    const int r0g = tid >> 2,        s0g = (tid & 3) * 8;
    const int r1g = (tid + 256) >> 2, s1g = ((tid + 256) & 3) * 8;

    const __nv_bfloat16* srcs[4] = {
        Ahi + (size_t)m0 * D_MODEL, Alo + (size_t)m0 * D_MODEL,
        Bhi + (size_t)n0 * D_MODEL, Blo + (size_t)n0 * D_MODEL };

    auto load_stage = [&](int s, int k0) {
        #pragma unroll
        for (int tile = 0; tile < 4; ++tile) {
            const __nv_bfloat16* src = srcs[tile];
            const uint32_t dbase = sbase + (uint32_t)(((s * 4 + tile) * T_ELEM) * 2);
            CP_ASYNC16(dbase + (uint32_t)((r0g * 40 + s0g) * 2),
                       src + (size_t)r0g * D_MODEL + k0 + s0g);
            CP_ASYNC16(dbase + (uint32_t)((r1g * 40 + s1g) * 2),
                       src + (size_t)r1g * D_MODEL + k0 + s1g);
        }
    };

    // ldmatrix per-thread byte offsets (shared by A and B tile math)
    const int lrow = (lane & 7) + ((lane >> 3) & 1) * 8;   // row within 16
    const int lcol = (lane >> 4) * 8;                      // k within 16
    const uint32_t offL = (uint32_t)((lrow * 40 + lcol) * 2);

    float acc[4][4][4];
    #pragma unroll
    for (int m = 0; m < 4; ++m)
        #pragma unroll
        for (int n = 0; n < 4; ++n)
            #pragma unroll
            for (int q = 0; q < 4; ++q) acc[m][n][q] = 0.f;

    auto compute_stage = [&](int s) {
        const uint32_t base = sbase + (uint32_t)((s * STG_E) * 2);
        #pragma unroll
        for (int kh = 0; kh < 2; ++kh) {
            uint32_t ah[4][4], al[4][4], bh[2][4], bl[2][4];
            #pragma unroll
            for (int m = 0; m < 4; ++m) {
                const uint32_t aaddr = base + offL
                    + (uint32_t)((((wm * 64 + m * 16) * 40) + kh * 16) * 2);
                LDSM_X4(ah[m][0], ah[m][1], ah[m][2], ah[m][3], aaddr);
                LDSM_X4(al[m][0], al[m][1], al[m][2], al[m][3], aaddr + T_ELEM * 2);
            }
            #pragma unroll
            for (int p = 0; p < 2; ++p) {
                const uint32_t baddr = base + (uint32_t)(2 * T_ELEM * 2) + offL
                    + (uint32_t)((((wn * 32 + p * 16) * 40) + kh * 16) * 2);
                LDSM_X4(bh[p][0], bh[p][1], bh[p][2], bh[p][3], baddr);
                LDSM_X4(bl[p][0], bl[p][1], bl[p][2], bl[p][3], baddr + T_ELEM * 2);
            }
            #pragma unroll
            for (int m = 0; m < 4; ++m)
                #pragma unroll
                for (int p = 0; p < 2; ++p)
                    #pragma unroll
                    for (int q = 0; q < 2; ++q) {
                        float* c = acc[m][p * 2 + q];
                        MMA16816(c, ah[m][0], ah[m][1], ah[m][2], ah[m][3],
                                 bh[p][q], bh[p][q + 2]);
                        MMA16816(c, ah[m][0], ah[m][1], ah[m][2], ah[m][3],
                                 bl[p][q], bl[p][q + 2]);
                        MMA16816(c, al[m][0], al[m][1], al[m][2], al[m][3],
                                 bh[p][q], bh[p][q + 2]);
                    }
        }
    };

    load_stage(0, 0);
    CP_COMMIT();

    const int nt = D_MODEL / BK;     // 64
    #pragma unroll 1
    for (int t = 0; t < nt; ++t) {
        if (t + 1 < nt) {
            load_stage((t + 1) & 1, (t + 1) * BK);
            CP_COMMIT();
            CP_WAIT(1);
        } else {
            CP_WAIT(0);
        }
        __syncthreads();
        compute_stage(t & 1);
        __syncthreads();
    }

    // epilogue
    const int er = lane >> 2;
    const int ec = (lane & 3) * 2;
    #pragma unroll
    for (int m = 0; m < 4; ++m) {
        const int gr = m0 + wm * 64 + m * 16 + er;
        #pragma unroll
        for (int n = 0; n < 4; ++n) {
            const int gc = n0 + wn * 32 + n * 8 + ec;
            if (gc < N) {
                float2 v0 = make_float2(acc[m][n][0], acc[m][n][1]);
                float2 v1 = make_float2(acc[m][n][2], acc[m][n][3]);
                if (EPI) {
                    const float2 r0v = *(const float2*)(resid + (size_t)gr * N + gc);
                    const float2 r1v = *(const float2*)(resid + (size_t)(gr + 8) * N + gc);
                    v0.x += r0v.x; v0.y += r0v.y;
                    v1.x += r1v.x; v1.y += r1v.y;
                }
                *(float2*)(C + (size_t)gr * N + gc) = v0;
                *(float2*)(C + (size_t)(gr + 8) * N + gc) = v1;
            }
        }
    }
}

// ------------------------------ conv + silu --------------------------------
__global__ __launch_bounds__(256)
void conv_silu_kernel(const float* __restrict__ cw, const float* __restrict__ cb)
{
    const int idx = blockIdx.x * 256 + threadIdx.x;
    const int d   = idx & (D_MODEL - 1);
    const int row = idx >> 11;
    const int t   = row & (T_LEN - 1);

    const float w0 = cw[d * 4 + 0], w1 = cw[d * 4 + 1];
    const float w2 = cw[d * 4 + 2], w3 = cw[d * 4 + 3];

    float acc = cb[d] + w3 * g_xz[(size_t)row * N_XZ + d];
    if (t >= 1) acc = fmaf(w2, g_xz[(size_t)(row - 1) * N_XZ + d], acc);
    if (t >= 2) acc = fmaf(w1, g_xz[(size_t)(row - 2) * N_XZ + d], acc);
    if (t >= 3) acc = fmaf(w0, g_xz[(size_t)(row - 3) * N_XZ + d], acc);

    const float s = acc / (1.0f + __expf(-acc));   // silu
    __nv_bfloat16 h, l; split1(s, h, l);
    g_a_hi[(size_t)row * D_MODEL + d] = h;
    g_a_lo[(size_t)row * D_MODEL + d] = l;
}

// ----------------------------- selective scan ------------------------------
__global__ __launch_bounds__(256)
void scan_kernel(const float* __restrict__ h0, const float* __restrict__ A_log,
                 const float* __restrict__ Dvec, float* __restrict__ h_out)
{
    constexpr int TC = 32;
    const int blk  = blockIdx.x;
    const int b    = blk >> 7;
    const int d0   = (blk & 127) * 16;
    const int tid  = threadIdx.x;
    const int warp = tid >> 5;
    const int lane = tid & 31;
    const int half = lane >> 4;
    const int n    = lane & 15;
    const int lc   = warp * 2 + half;
    const int dch  = d0 + lc;

    const float A_n = -__expf(A_log[dch * D_STATE + n]);
    const float Dd  = Dvec[dch];
    float h = h0[((size_t)b * D_MODEL + dch) * D_STATE + n];

    __shared__ float sD[TC][16];
    __shared__ float sX[TC][16];
    __shared__ float sB[TC][16];
    __shared__ float sC[TC][16];
    __shared__ float sY[TC][16];

    for (int c = 0; c < T_LEN / TC; ++c) {
        const int t0 = c * TC;
        #pragma unroll
        for (int i = tid; i < TC * 16; i += 256) {
            const int tt = i >> 4, dd = i & 15;
            const size_t row = (size_t)(b * T_LEN + t0 + tt);
            const float dr = g_proj[row * N_PROJ + d0 + dd];
            sD[tt][dd] = (dr > 20.f) ? dr : log1pf(__expf(dr));   // softplus
            sX[tt][dd] = __bfloat162float(g_a_hi[row * D_MODEL + d0 + dd])
                       + __bfloat162float(g_a_lo[row * D_MODEL + d0 + dd]);
            sB[tt][dd] = g_proj[row * N_PROJ + D_MODEL + dd];
            sC[tt][dd] = g_proj[row * N_PROJ + D_MODEL + D_STATE + dd];
        }
        __syncthreads();

        #pragma unroll 4
        for (int tt = 0; tt < TC; ++tt) {
            const float dt = sD[tt][lc];
            const float xv = sX[tt][lc];
            const float bv = sB[tt][n];
            const float cv = sC[tt][n];
            h = fmaf(__expf(dt * A_n), h, (dt * xv) * bv);
            float p = h * cv;
            p += __shfl_xor_sync(0xffffffffu, p, 8);
            p += __shfl_xor_sync(0xffffffffu, p, 4);
            p += __shfl_xor_sync(0xffffffffu, p, 2);
            p += __shfl_xor_sync(0xffffffffu, p, 1);
            if (n == 0) sY[tt][lc] = fmaf(Dd, xv, p);
        }
        __syncthreads();

        #pragma unroll
        for (int i = tid; i < TC * 16; i += 256) {
            const int tt = i >> 4, dd = i & 15;
            const size_t row = (size_t)(b * T_LEN + t0 + tt);
            const float z = g_xz[row * N_XZ + D_MODEL + d0 + dd];
            const float y = sY[tt][dd] * (z / (1.0f + __expf(-z)));
            __nv_bfloat16 hh, ll; split1(y, hh, ll);
            g_a_hi[row * D_MODEL + d0 + dd] = hh;
            g_a_lo[row * D_MODEL + d0 + dd] = ll;
        }
        __syncthreads();
    }

    if (h_out)
        h_out[((size_t)b * D_MODEL + dch) * D_STATE + n] = h;
}

// ----------------------------------- host ----------------------------------
static __nv_bfloat16 *s_a_hi, *s_a_lo, *s_b_hi, *s_b_lo;
static float *s_xz, *s_proj;
static bool s_init = false;

extern "C" void kernel_launch(void* const* d_in, const int* in_sizes, int n_in,
                              void* d_out, int out_size)
{
    const float* x          = (const float*)d_in[0];
    const float* h0         = (const float*)d_in[1];
    const float* norm_w     = (const float*)d_in[2];
    const float* in_proj_w  = (const float*)d_in[3];
    const float* conv_w     = (const float*)d_in[4];
    const float* conv_b     = (const float*)d_in[5];
    const float* x_proj_w   = (const float*)d_in[6];
    const float* A_log      = (const float*)d_in[7];
    const float* Dvec       = (const float*)d_in[8];
    const float* out_proj_w = (const float*)d_in[9];

    if (!s_init) {
        cudaGetSymbolAddress((void**)&s_a_hi, g_a_hi);
        cudaGetSymbolAddress((void**)&s_a_lo, g_a_lo);
        cudaGetSymbolAddress((void**)&s_b_hi, g_b_hi);
        cudaGetSymbolAddress((void**)&s_b_lo, g_b_lo);
        cudaGetSymbolAddress((void**)&s_xz,   g_xz);
        cudaGetSymbolAddress((void**)&s_proj, g_proj);
        cudaFuncSetAttribute(gemm_bf3, cudaFuncAttributeMaxDynamicSharedMemorySize, SMEM_GEMM);
        s_init = true;
    }

    float* out = (float*)d_out;
    const size_t out_elems = (size_t)M_TOK * D_MODEL;
    float* h_out = ((size_t)out_size >= out_elems + (size_t)B_SZ * D_MODEL * D_STATE)
                       ? out + out_elems : nullptr;

    // 1. rmsnorm -> (a_hi, a_lo)
    rmsnorm_kernel<<<M_TOK, 256>>>(x, norm_w);

    // 2. split in_proj_w; GEMM1: xz (f32), M=4096 N=4096 K=2048
    split_kernel<<<(N_XZ * D_MODEL / 4 + 255) / 256, 256>>>(in_proj_w, N_XZ * D_MODEL / 4);
    gemm_bf3<<<dim3(N_XZ / 128, M_TOK / 128), 256, SMEM_GEMM>>>(
        s_a_hi, s_a_lo, s_b_hi, s_b_lo, s_xz, x, N_XZ, 0);

    // 3. conv + silu -> x_ssm split into (a_hi, a_lo)
    conv_silu_kernel<<<(M_TOK * D_MODEL) / 256, 256>>>(conv_w, conv_b);

    // 4. split x_proj_w; GEMM2: proj (f32), N=2080 (guarded)
    split_kernel<<<(N_PROJ * D_MODEL / 4 + 255) / 256, 256>>>(x_proj_w, N_PROJ * D_MODEL / 4);
    gemm_bf3<<<dim3((N_PROJ + 127) / 128, M_TOK / 128), 256, SMEM_GEMM>>>(
        s_a_hi, s_a_lo, s_b_hi, s_b_lo, s_proj, x, N_PROJ, 0);

    // 5. selective scan: gated y -> (a_hi, a_lo); h_new tail of d_out
    scan_kernel<<<B_SZ * (D_MODEL / 16), 256>>>(h0, A_log, Dvec, h_out);

    // 6. split out_proj_w; GEMM3: out = x + y @ out_proj^T
    split_kernel<<<(D_MODEL * D_MODEL / 4 + 255) / 256, 256>>>(out_proj_w, D_MODEL * D_MODEL / 4);
    gemm_bf3<<<dim3(D_MODEL / 128, M_TOK / 128), 256, SMEM_GEMM>>>(
        s_a_hi, s_a_lo, s_b_hi, s_b_lo, out, x, D_MODEL, 1);
}